// round 1
// baseline (speedup 1.0000x reference)
#include <cuda_runtime.h>

// Problem constants (fixed by reference)
#define NN     1024     // neurons
#define BATCH  128
#define SEQ    500
#define INDIM  24
#define DTC    0.1f

// GEMM tiling
#define BM 16
#define BN 64
#define BK 64

// Persistent recurrent state r[b][n] (alloc-free scratch)
__device__ float g_r[BATCH * NN];

__global__ void init_kernel() {
    int i = blockIdx.x * blockDim.x + threadIdx.x;
    if (i < BATCH * NN) g_r[i] = 0.0f;
}

__global__ void final_kernel(float* __restrict__ out_tail) {
    int i = blockIdx.x * blockDim.x + threadIdx.x;
    if (i < BATCH * NN) out_tail[i] = g_r[i];
}

// One recurrence step:
//   x[b,n]   = sum_k relu(r[b,k]) * sign[k] * W[n,k]  +  sum_i u[b,t,i] * B[n,i]
//   act      = 16 / (1 + exp(6 - 0.8*x))        (== 8*(1+tanh(0.4x-3)))
//   r_new    = r + (DT/tau[n]) * (act - r)
//   out[b,t,n] = r_new ; g_r[b,n] = r_new
__global__ __launch_bounds__(256) void step_kernel(
    const float* __restrict__ u,
    const float* __restrict__ W,
    const float* __restrict__ Bmat,
    const float* __restrict__ ds,     // dales_sign
    const float* __restrict__ tau,
    float* __restrict__ out,
    int t)
{
    // As[k][m], padded to 20 floats per row: 16B-aligned float4 rows, 4-way STS conflict max
    __shared__ __align__(16) float As[BK][20];
    __shared__ float Ws[BN][BK + 1];          // [n][k], +1 pad -> conflict-free LDS
    __shared__ float Bs[BN][INDIM];
    __shared__ float Us[BM][INDIM];

    const int tid = threadIdx.x;
    const int tn  = tid & 63;                 // 0..63  (neuron within tile)
    const int tg  = tid >> 6;                 // 0..3   (batch group)
    const int n0  = blockIdx.x * BN;
    const int b0  = blockIdx.y * BM;
    const int n   = n0 + tn;

    // Load B tile and u[b, t, :] slice for the epilogue drive
    for (int e = tid; e < BN * INDIM; e += 256) {
        int nn = e / INDIM, i = e % INDIM;
        Bs[nn][i] = Bmat[(n0 + nn) * INDIM + i];
    }
    for (int e = tid; e < BM * INDIM; e += 256) {
        int m = e / INDIM, i = e % INDIM;
        Us[m][i] = u[((size_t)(b0 + m) * SEQ + t) * INDIM + i];
    }

    float acc0 = 0.f, acc1 = 0.f, acc2 = 0.f, acc3 = 0.f;

    // Register staging for the next K-tile (software pipeline, single smem buffer)
    float rW[16];
    float rA[4];

    // Per-thread fixed k-lane within a tile: k = tn (since 256 % 64 == 0)
    // A rows: m = tg + 4*j ; W rows: n_row = tg + 4*j
    {
        const int kk = tn;                    // k within tile 0
        const float s = ds[kk];
        #pragma unroll
        for (int j = 0; j < 4; ++j) {
            float rv = g_r[(size_t)(b0 + tg + 4 * j) * NN + kk];
            rA[j] = fmaxf(rv, 0.f) * s;
        }
        #pragma unroll
        for (int j = 0; j < 16; ++j) {
            rW[j] = W[(size_t)(n0 + tg + 4 * j) * NN + kk];
        }
    }

    #pragma unroll 1
    for (int kt = 0; kt < NN / BK; ++kt) {
        __syncthreads();   // previous compute done before overwrite
        // Commit staged registers to shared
        #pragma unroll
        for (int j = 0; j < 4; ++j)  As[tn][tg + 4 * j] = rA[j];
        #pragma unroll
        for (int j = 0; j < 16; ++j) Ws[tg + 4 * j][tn] = rW[j];
        __syncthreads();

        // Prefetch next tile (LDG latency overlaps the compute below)
        if (kt + 1 < NN / BK) {
            const int kk = (kt + 1) * BK + tn;
            const float s = ds[kk];
            #pragma unroll
            for (int j = 0; j < 4; ++j) {
                float rv = g_r[(size_t)(b0 + tg + 4 * j) * NN + kk];
                rA[j] = fmaxf(rv, 0.f) * s;
            }
            #pragma unroll
            for (int j = 0; j < 16; ++j) {
                rW[j] = W[(size_t)(n0 + tg + 4 * j) * NN + (kt + 1) * BK + tn];
            }
        }

        // MAC over this K-tile: each thread -> 4 batch rows, 1 neuron
        #pragma unroll 8
        for (int k = 0; k < BK; ++k) {
            const float w = Ws[tn][k];
            const float4 a = *reinterpret_cast<const float4*>(&As[k][4 * tg]);
            acc0 = fmaf(a.x, w, acc0);
            acc1 = fmaf(a.y, w, acc1);
            acc2 = fmaf(a.z, w, acc2);
            acc3 = fmaf(a.w, w, acc3);
        }
    }

    // Epilogue: drive + activation + state update
    const float an = DTC / tau[n];
    float accs[4] = {acc0, acc1, acc2, acc3};

    #pragma unroll
    for (int j = 0; j < 4; ++j) {
        const int m = 4 * tg + j;
        float d = 0.f;
        #pragma unroll
        for (int i = 0; i < INDIM; ++i)
            d = fmaf(Us[m][i], Bs[tn][i], d);

        const float x = accs[j] + d;
        // act = 8*(1+tanh(0.4x-3)) == 16 / (1 + exp(6 - 0.8x))
        const float e = __expf(fmaf(-0.8f, x, 6.0f));
        const float act = 16.0f / (1.0f + e);

        const size_t ridx = (size_t)(b0 + m) * NN + n;
        const float r = g_r[ridx];
        const float rn = fmaf(an, act - r, r);
        g_r[ridx] = rn;
        out[((size_t)(b0 + m) * SEQ + t) * NN + n] = rn;
    }
}

extern "C" void kernel_launch(void* const* d_in, const int* in_sizes, int n_in,
                              void* d_out, int out_size) {
    const float* u    = (const float*)d_in[0];   // (128, 500, 24)
    const float* W    = (const float*)d_in[1];   // (1024, 1024)
    const float* Bm   = (const float*)d_in[2];   // (1024, 24)
    const float* ds   = (const float*)d_in[3];   // (1024,)
    const float* tau  = (const float*)d_in[4];   // (1024,)
    float* out = (float*)d_out;                  // r_seq (128,500,1024) ++ r_final (1,128,1024)

    init_kernel<<<(BATCH * NN + 255) / 256, 256>>>();

    dim3 grid(NN / BN, BATCH / BM);              // (16, 8) = 128 CTAs
    for (int t = 0; t < SEQ; ++t) {
        step_kernel<<<grid, 256>>>(u, W, Bm, ds, tau, out, t);
    }

    final_kernel<<<(BATCH * NN + 255) / 256, 256>>>(out + (size_t)BATCH * SEQ * NN);
}

// round 4
// speedup vs baseline: 2.9730x; 2.9730x over previous
#include <cuda_runtime.h>
#include <cuda_bf16.h>
#include <cstdint>

#define NN     1024
#define BATCH  128
#define SEQ    500
#define INDIM  24

// ---------------- device scratch (alloc-free) ----------------
__device__ __align__(16) __nv_bfloat16 g_Ahi[BATCH * NN];   // [b][k] row-major
__device__ __align__(16) __nv_bfloat16 g_Alo[BATCH * NN];
__device__ __align__(16) __nv_bfloat16 g_Whi[NN * NN];      // [n][k] row-major, sign folded
__device__ __align__(16) __nv_bfloat16 g_Wlo[NN * NN];
__device__ float g_partial[8 * BATCH * NN];                 // [kc][b][n]
__device__ unsigned g_ctr;                                  // grid barrier counter

// ---------------- warp MMA helpers (portable PTX, sm_80+) ----------------
__device__ __forceinline__ uint32_t smem_u32(const void* p) {
    uint32_t a;
    asm("{ .reg .u64 t; cvta.to.shared.u64 t, %1; cvt.u32.u64 %0, t; }" : "=r"(a) : "l"(p));
    return a;
}
__device__ __forceinline__ void ldsm_x4(uint32_t* r, uint32_t addr) {
    asm volatile("ldmatrix.sync.aligned.m8n8.x4.shared.b16 {%0,%1,%2,%3}, [%4];"
        : "=r"(r[0]), "=r"(r[1]), "=r"(r[2]), "=r"(r[3]) : "r"(addr));
}
__device__ __forceinline__ void ldsm_x2(uint32_t* r, uint32_t addr) {
    asm volatile("ldmatrix.sync.aligned.m8n8.x2.shared.b16 {%0,%1}, [%2];"
        : "=r"(r[0]), "=r"(r[1]) : "r"(addr));
}
__device__ __forceinline__ void mma_bf16(float* d, const uint32_t* a, const uint32_t* b) {
    asm volatile("mma.sync.aligned.m16n8k16.row.col.f32.bf16.bf16.f32 "
        "{%0,%1,%2,%3}, {%4,%5,%6,%7}, {%8,%9}, {%0,%1,%2,%3};"
        : "+f"(d[0]), "+f"(d[1]), "+f"(d[2]), "+f"(d[3])
        : "r"(a[0]), "r"(a[1]), "r"(a[2]), "r"(a[3]), "r"(b[0]), "r"(b[1]));
}

// grid barrier: all 128 CTAs co-resident (grid == 128 <= #SMs, 1 CTA/SM)
__device__ __forceinline__ void grid_barrier(unsigned target) {
    __syncthreads();
    if (threadIdx.x == 0) {
        __threadfence();                       // release my CTA's prior writes
        atomicAdd(&g_ctr, 1u);
        while (*(volatile unsigned*)&g_ctr < target) { __nanosleep(32); }
        __threadfence();                       // acquire
    }
    __syncthreads();
}

// ---------------- init ----------------
__global__ void init_kernel() {
    int i = blockIdx.x * blockDim.x + threadIdx.x;
    if (i == 0) g_ctr = 0u;
    if (i < BATCH * NN) {
        g_Ahi[i] = __float2bfloat16(0.0f);
        g_Alo[i] = __float2bfloat16(0.0f);
    }
}

// ---------------- W prep: fold dales sign, split hi/lo ----------------
__global__ __launch_bounds__(128) void wprep_kernel(const float* __restrict__ W,
                                                    const float* __restrict__ ds) {
    int gid = blockIdx.x * 128 + threadIdx.x;
    int base = gid << 3;
    int k0 = base & (NN - 1);
    union { unsigned short u[8]; uint4 v; } hi, lo;
    #pragma unroll
    for (int j = 0; j < 8; ++j) {
        float w = W[base + j] * ds[k0 + j];
        __nv_bfloat16 h = __float2bfloat16(w);
        __nv_bfloat16 l = __float2bfloat16(w - __bfloat162float(h));
        hi.u[j] = *reinterpret_cast<unsigned short*>(&h);
        lo.u[j] = *reinterpret_cast<unsigned short*>(&l);
    }
    *reinterpret_cast<uint4*>(g_Whi + base) = hi.v;
    *reinterpret_cast<uint4*>(g_Wlo + base) = lo.v;
}

// ---------------- persistent kernel: all 500 steps ----------------
// GEMM role: CTA c -> nt = c&15 (64-neuron tile), kc = c>>4 (128-wide K chunk)
//   partial[kc][b][nt*64..] = A(hi/lo) @ W(hi/lo)^T   (3-term compensated bf16)
// ACT role:  CTA c -> nt_a = c&15 (neuron tile), kg = c>>4 (16-batch group)
//   thread owns (b = kg*16 + tid>>4, n = nt_a*64 + (tid&15)*4); r state in registers.
#define LDA 136                       // 128 + 8 pad elems; row stride 272 B
#define SW_HI 0
#define SW_LO 17408
#define SA_HI 34816
#define SA_LO 69632
#define SM_BS 104448                  // 64 x 24 fp32
#define SM_US 110592                  // 16 x 24 fp32
#define SMEM_TOTAL 112128

__global__ __launch_bounds__(256, 1) void persist_kernel(
    const float* __restrict__ u,
    const float* __restrict__ Bmat,
    const float* __restrict__ tau,
    float* __restrict__ out)
{
    extern __shared__ char smem[];
    const uint32_t sb = smem_u32(smem);
    const int tid  = threadIdx.x;
    const int lane = tid & 31;
    const int wid  = tid >> 5;
    const int wr = wid >> 2;          // M half (64 rows)
    const int wc = wid & 3;           // N quarter (16 cols)
    const int c  = blockIdx.x;
    const int nt = c & 15;
    const int kc = c >> 4;

    // ---- persistent W tile (hi+lo) into smem, once ----
    #pragma unroll 2
    for (int i = tid; i < 1024; i += 256) {
        const int row = i >> 4, c16 = i & 15;
        const int gsrc = (nt * 64 + row) * NN + kc * 128 + c16 * 8;
        const int dst = (row * LDA + c16 * 8) * 2;
        *reinterpret_cast<uint4*>(smem + SW_HI + dst) = *reinterpret_cast<const uint4*>(g_Whi + gsrc);
        *reinterpret_cast<uint4*>(smem + SW_LO + dst) = *reinterpret_cast<const uint4*>(g_Wlo + gsrc);
    }

    // ---- persistent B tile for the act role (64 x 24 fp32), once ----
    float* Bs = reinterpret_cast<float*>(smem + SM_BS);
    {
        const int nt_a = c & 15;
        for (int i = tid; i < 384; i += 256) {        // 384 float4
            const int row = i / 6, q = i % 6;
            *reinterpret_cast<float4*>(&Bs[row * 24 + q * 4]) =
                *reinterpret_cast<const float4*>(Bmat + (size_t)(nt_a * 64 + row) * INDIM + q * 4);
        }
    }

    // ---- act-role per-thread constants and register state ----
    const int kg   = c >> 4;
    const int b_a  = kg * 16 + (tid >> 4);
    const int nl_a = (tid & 15) * 4;                  // n within tile
    const int n_a  = (c & 15) * 64 + nl_a;
    float an[4], rr[4];
    {
        const float4 t4 = *reinterpret_cast<const float4*>(&tau[n_a]);
        an[0] = 0.1f / t4.x; an[1] = 0.1f / t4.y; an[2] = 0.1f / t4.z; an[3] = 0.1f / t4.w;
        rr[0] = rr[1] = rr[2] = rr[3] = 0.f;
    }
    float* Us = reinterpret_cast<float*>(smem + SM_US);

    const int ra = lane & 15, ca = (lane >> 4) << 3;        // A ldmatrix mapping
    const int rb = lane & 7,  cb = ((lane >> 3) & 1) << 3;  // B ldmatrix mapping
    const int rq = lane >> 2, cq = (lane & 3) * 2;          // C fragment mapping

    unsigned bar = 0;

    for (int t = 0; t < SEQ; ++t) {
        // ======== phase A: load A chunk + u slice, GEMM, write partials ========
        #pragma unroll 4
        for (int i = tid; i < 2048; i += 256) {             // A: 128 rows x 16 uint4
            const int row = i >> 4, c16 = i & 15;
            const int gsrc = row * NN + kc * 128 + c16 * 8;
            const int dst = (row * LDA + c16 * 8) * 2;
            *reinterpret_cast<uint4*>(smem + SA_HI + dst) = *reinterpret_cast<const uint4*>(g_Ahi + gsrc);
            *reinterpret_cast<uint4*>(smem + SA_LO + dst) = *reinterpret_cast<const uint4*>(g_Alo + gsrc);
        }
        if (tid < 96) {                                     // u[b,t,:] for 16 batches
            const int bi = tid / 6, q = tid % 6;
            *reinterpret_cast<float4*>(&Us[bi * 24 + q * 4]) =
                *reinterpret_cast<const float4*>(u + ((size_t)(kg * 16 + bi) * SEQ + t) * INDIM + q * 4);
        }
        __syncthreads();

        float acc[4][2][4];
        #pragma unroll
        for (int mi = 0; mi < 4; ++mi)
            #pragma unroll
            for (int ni = 0; ni < 2; ++ni)
                #pragma unroll
                for (int q = 0; q < 4; ++q) acc[mi][ni][q] = 0.f;

        #pragma unroll
        for (int ks = 0; ks < 8; ++ks) {
            const int k0 = ks * 16;
            uint32_t ah[4][4], al[4][4], bh[2][2], bl[2][2];
            #pragma unroll
            for (int mi = 0; mi < 4; ++mi) {
                const uint32_t ba = sb + ((wr * 64 + mi * 16 + ra) * LDA + k0 + ca) * 2;
                ldsm_x4(ah[mi], ba + SA_HI);
                ldsm_x4(al[mi], ba + SA_LO);
            }
            #pragma unroll
            for (int ni = 0; ni < 2; ++ni) {
                const uint32_t bb = sb + ((wc * 16 + ni * 8 + rb) * LDA + k0 + cb) * 2;
                ldsm_x2(bh[ni], bb + SW_HI);
                ldsm_x2(bl[ni], bb + SW_LO);
            }
            #pragma unroll
            for (int mi = 0; mi < 4; ++mi)
                #pragma unroll
                for (int ni = 0; ni < 2; ++ni) {
                    mma_bf16(acc[mi][ni], ah[mi], bh[ni]);
                    mma_bf16(acc[mi][ni], al[mi], bh[ni]);
                    mma_bf16(acc[mi][ni], ah[mi], bl[ni]);
                }
        }

        const int n0 = nt * 64 + wc * 16;
        #pragma unroll
        for (int mi = 0; mi < 4; ++mi) {
            const int b0 = wr * 64 + mi * 16 + rq;
            #pragma unroll
            for (int ni = 0; ni < 2; ++ni) {
                const int col = n0 + ni * 8 + cq;
                float2 v0 = {acc[mi][ni][0], acc[mi][ni][1]};
                float2 v1 = {acc[mi][ni][2], acc[mi][ni][3]};
                *reinterpret_cast<float2*>(&g_partial[((kc * 128 + b0) << 10) + col]) = v0;
                *reinterpret_cast<float2*>(&g_partial[((kc * 128 + b0 + 8) << 10) + col]) = v1;
            }
        }

        grid_barrier(++bar * 128u);

        // ======== phase B: reduce partials + drive + activation + update ========
        float s[4] = {0.f, 0.f, 0.f, 0.f};
        #pragma unroll
        for (int kq = 0; kq < 8; ++kq) {
            const float4 p = *reinterpret_cast<const float4*>(&g_partial[((kq * 128 + b_a) << 10) + n_a]);
            s[0] += p.x; s[1] += p.y; s[2] += p.z; s[3] += p.w;
        }
        {
            const float* uu = &Us[(tid >> 4) * 24];
            #pragma unroll
            for (int j = 0; j < 4; ++j) {
                const float* bp = &Bs[(nl_a + j) * 24];
                float d = 0.f;
                #pragma unroll
                for (int i = 0; i < INDIM; ++i) d = fmaf(uu[i], bp[i], d);
                s[j] += d;
            }
        }
        float rn[4];
        #pragma unroll
        for (int j = 0; j < 4; ++j) {
            const float e = __expf(fmaf(-0.8f, s[j], 6.0f));
            const float act = __fdividef(16.0f, 1.0f + e);
            rn[j] = fmaf(an[j], act - rr[j], rr[j]);
            rr[j] = rn[j];
        }
        float4 rno = {rn[0], rn[1], rn[2], rn[3]};
        *reinterpret_cast<float4*>(&out[((size_t)b_a * SEQ + t) * NN + n_a]) = rno;
        if (t == SEQ - 1)
            *reinterpret_cast<float4*>(&out[(size_t)BATCH * SEQ * NN + b_a * NN + n_a]) = rno;

        union { unsigned short u16[4]; uint2 v; } ahi, alo;
        #pragma unroll
        for (int j = 0; j < 4; ++j) {
            const float a = fmaxf(rn[j], 0.f);
            __nv_bfloat16 h = __float2bfloat16(a);
            __nv_bfloat16 l = __float2bfloat16(a - __bfloat162float(h));
            ahi.u16[j] = *reinterpret_cast<unsigned short*>(&h);
            alo.u16[j] = *reinterpret_cast<unsigned short*>(&l);
        }
        *reinterpret_cast<uint2*>(g_Ahi + b_a * NN + n_a) = ahi.v;
        *reinterpret_cast<uint2*>(g_Alo + b_a * NN + n_a) = alo.v;

        grid_barrier(++bar * 128u);
    }
}

// ---------------- launch (3 graph nodes) ----------------
extern "C" void kernel_launch(void* const* d_in, const int* in_sizes, int n_in,
                              void* d_out, int out_size) {
    const float* u   = (const float*)d_in[0];
    const float* W   = (const float*)d_in[1];
    const float* Bm  = (const float*)d_in[2];
    const float* ds  = (const float*)d_in[3];
    const float* tau = (const float*)d_in[4];
    float* out = (float*)d_out;

    static int smem_set = 0;
    if (!smem_set) {
        cudaFuncSetAttribute(persist_kernel, cudaFuncAttributeMaxDynamicSharedMemorySize, SMEM_TOTAL);
        smem_set = 1;
    }

    init_kernel<<<(BATCH * NN + 255) / 256, 256>>>();
    wprep_kernel<<<1024, 128>>>(W, ds);
    persist_kernel<<<128, 256, SMEM_TOTAL>>>(u, Bm, tau, out);
}

// round 5
// speedup vs baseline: 3.3650x; 1.1319x over previous
#include <cuda_runtime.h>
#include <cuda_bf16.h>
#include <cstdint>

#define NN     1024
#define BATCH  128
#define SEQ    500
#define INDIM  24

// ---------------- device scratch (alloc-free) ----------------
__device__ __align__(16) __nv_bfloat16 g_A[BATCH * NN];     // relu(r) bf16, [b][k]
__device__ __align__(16) __nv_bfloat16 g_Whi[NN * NN];      // [n][k], sign folded
__device__ __align__(16) __nv_bfloat16 g_Wlo[NN * NN];      // bf16 residual of W
__device__ float g_partial[8 * BATCH * NN];                 // [kc][b][n]
__device__ unsigned g_ctr;                                  // grid barrier counter

// ---------------- PTX helpers (portable, sm_80+) ----------------
__device__ __forceinline__ uint32_t smem_u32(const void* p) {
    uint32_t a;
    asm("{ .reg .u64 t; cvta.to.shared.u64 t, %1; cvt.u32.u64 %0, t; }" : "=r"(a) : "l"(p));
    return a;
}
__device__ __forceinline__ void ldsm_x4(uint32_t* r, uint32_t addr) {
    asm volatile("ldmatrix.sync.aligned.m8n8.x4.shared.b16 {%0,%1,%2,%3}, [%4];"
        : "=r"(r[0]), "=r"(r[1]), "=r"(r[2]), "=r"(r[3]) : "r"(addr));
}
__device__ __forceinline__ void mma_bf16(float* d, const uint32_t* a, const uint32_t* b) {
    asm volatile("mma.sync.aligned.m16n8k16.row.col.f32.bf16.bf16.f32 "
        "{%0,%1,%2,%3}, {%4,%5,%6,%7}, {%8,%9}, {%0,%1,%2,%3};"
        : "+f"(d[0]), "+f"(d[1]), "+f"(d[2]), "+f"(d[3])
        : "r"(a[0]), "r"(a[1]), "r"(a[2]), "r"(a[3]), "r"(b[0]), "r"(b[1]));
}

// grid barrier: 128 CTAs co-resident (1/SM). release-arrive + acquire-poll.
__device__ __forceinline__ void grid_barrier(unsigned target) {
    __syncthreads();
    if (threadIdx.x == 0) {
        asm volatile("red.release.gpu.add.u32 [%0], %1;" :: "l"(&g_ctr), "r"(1u) : "memory");
        unsigned v;
        do {
            asm volatile("ld.acquire.gpu.b32 %0, [%1];" : "=r"(v) : "l"(&g_ctr) : "memory");
        } while (v < target);
    }
    __syncthreads();
}

// ---------------- W prep: fold dales sign, split hi/lo; reset barrier ctr ----
__global__ __launch_bounds__(128) void wprep_kernel(const float* __restrict__ W,
                                                    const float* __restrict__ ds) {
    int gid = blockIdx.x * 128 + threadIdx.x;
    if (gid == 0) g_ctr = 0u;
    int base = gid << 3;
    int k0 = base & (NN - 1);
    union { unsigned short u[8]; uint4 v; } hi, lo;
    #pragma unroll
    for (int j = 0; j < 8; ++j) {
        float w = W[base + j] * ds[k0 + j];
        __nv_bfloat16 h = __float2bfloat16(w);
        __nv_bfloat16 l = __float2bfloat16(w - __bfloat162float(h));
        hi.u[j] = *reinterpret_cast<unsigned short*>(&h);
        lo.u[j] = *reinterpret_cast<unsigned short*>(&l);
    }
    *reinterpret_cast<uint4*>(g_Whi + base) = hi.v;
    *reinterpret_cast<uint4*>(g_Wlo + base) = lo.v;
}

// ---------------- persistent kernel: all 500 steps ----------------
// GEMM role: CTA c -> nt = c&15 (64 neurons), kc = c>>4 (128-wide K chunk)
// ACT role:  CTA c -> nt (same), kg = c>>4 (16-batch group); r in registers.
#define LDA 136                       // 128 + 8 pad elems; row stride 272 B
#define SW_HI 0
#define SW_LO 17408
#define SA    34816
#define SM_BS 69632                   // 64 x 24 fp32
#define SM_US 75776                   // 16 x 24 fp32
#define SMEM_TOTAL 77312

__global__ __launch_bounds__(256, 1) void persist_kernel(
    const float* __restrict__ u,
    const float* __restrict__ Bmat,
    const float* __restrict__ tau,
    float* __restrict__ out)
{
    extern __shared__ char smem[];
    const uint32_t sb = smem_u32(smem);
    const int tid  = threadIdx.x;
    const int lane = tid & 31;
    const int wid  = tid >> 5;
    const int wr = wid >> 2;          // M half (64 rows)
    const int wc = wid & 3;           // N quarter (16 cols)
    const int c  = blockIdx.x;
    const int nt = c & 15;
    const int kc = c >> 4;

    // ---- persistent W tile (hi+lo) into smem, once ----
    #pragma unroll 2
    for (int i = tid; i < 1024; i += 256) {
        const int row = i >> 4, c16 = i & 15;
        const int gsrc = (nt * 64 + row) * NN + kc * 128 + c16 * 8;
        const int dst = (row * LDA + c16 * 8) * 2;
        *reinterpret_cast<uint4*>(smem + SW_HI + dst) = *reinterpret_cast<const uint4*>(g_Whi + gsrc);
        *reinterpret_cast<uint4*>(smem + SW_LO + dst) = *reinterpret_cast<const uint4*>(g_Wlo + gsrc);
    }

    // ---- persistent B tile (act role), once ----
    float* Bs = reinterpret_cast<float*>(smem + SM_BS);
    for (int i = tid; i < 384; i += 256) {            // 384 float4
        const int row = i / 6, q = i % 6;
        *reinterpret_cast<float4*>(&Bs[row * 24 + q * 4]) =
            *reinterpret_cast<const float4*>(Bmat + (size_t)(nt * 64 + row) * INDIM + q * 4);
    }

    // ---- act-role constants + register state ----
    const int kg   = c >> 4;
    const int b_a  = kg * 16 + (tid >> 4);
    const int nl_a = (tid & 15) * 4;
    const int n_a  = nt * 64 + nl_a;
    float an[4], rr[4];
    {
        const float4 t4 = *reinterpret_cast<const float4*>(&tau[n_a]);
        an[0] = 0.1f / t4.x; an[1] = 0.1f / t4.y; an[2] = 0.1f / t4.z; an[3] = 0.1f / t4.w;
        rr[0] = rr[1] = rr[2] = rr[3] = 0.f;
    }
    float* Us = reinterpret_cast<float*>(smem + SM_US);

    const int ra = lane & 15, ca = (lane >> 4) << 3;               // A ldmatrix map
    const int rbx = wc * 16 + ((lane >> 4) & 1) * 8 + (lane & 7);  // B ldmatrix.x4 row
    const int cbx = ((lane >> 3) & 1) << 3;                        // B ldmatrix.x4 col
    const int rq = lane >> 2, cq = (lane & 3) * 2;                 // C fragment map

    unsigned bar = 0;

    for (int t = 0; t < SEQ; ++t) {
        // ---- stage loads for this step ----
        if (tid < 96) {                                   // u[b,t,:] for 16 batches
            const int bi = tid / 6, q = tid % 6;
            *reinterpret_cast<float4*>(&Us[bi * 24 + q * 4]) =
                *reinterpret_cast<const float4*>(u + ((size_t)(kg * 16 + bi) * SEQ + t) * INDIM + q * 4);
        }
        if (t > 0) {
            #pragma unroll 4
            for (int i = tid; i < 2048; i += 256) {       // A: 128 rows x 16 uint4
                const int row = i >> 4, c16 = i & 15;
                *reinterpret_cast<uint4*>(smem + SA + (row * LDA + c16 * 8) * 2) =
                    *reinterpret_cast<const uint4*>(g_A + row * NN + kc * 128 + c16 * 8);
            }
        }
        __syncthreads();

        // ---- GEMM + partial store (skip at t=0: A == 0) ----
        if (t > 0) {
            float acc[4][2][4];
            #pragma unroll
            for (int mi = 0; mi < 4; ++mi)
                #pragma unroll
                for (int ni = 0; ni < 2; ++ni)
                    #pragma unroll
                    for (int q = 0; q < 4; ++q) acc[mi][ni][q] = 0.f;

            #pragma unroll
            for (int ks = 0; ks < 8; ++ks) {
                const int k0 = ks * 16;
                uint32_t ah[4][4], bh4[4], bl4[4];
                #pragma unroll
                for (int mi = 0; mi < 4; ++mi)
                    ldsm_x4(ah[mi], sb + SA + ((wr * 64 + mi * 16 + ra) * LDA + k0 + ca) * 2);
                {
                    const uint32_t bb = sb + (rbx * LDA + k0 + cbx) * 2;
                    ldsm_x4(bh4, bb + SW_HI);
                    ldsm_x4(bl4, bb + SW_LO);
                }
                #pragma unroll
                for (int mi = 0; mi < 4; ++mi)
                    #pragma unroll
                    for (int ni = 0; ni < 2; ++ni) {
                        mma_bf16(acc[mi][ni], ah[mi], &bh4[ni * 2]);
                        mma_bf16(acc[mi][ni], ah[mi], &bl4[ni * 2]);
                    }
            }

            const int n0 = nt * 64 + wc * 16;
            #pragma unroll
            for (int mi = 0; mi < 4; ++mi) {
                const int b0 = wr * 64 + mi * 16 + rq;
                #pragma unroll
                for (int ni = 0; ni < 2; ++ni) {
                    const int col = n0 + ni * 8 + cq;
                    float2 v0 = {acc[mi][ni][0], acc[mi][ni][1]};
                    float2 v1 = {acc[mi][ni][2], acc[mi][ni][3]};
                    *reinterpret_cast<float2*>(&g_partial[((kc * 128 + b0) << 10) + col]) = v0;
                    *reinterpret_cast<float2*>(&g_partial[((kc * 128 + b0 + 8) << 10) + col]) = v1;
                }
            }
            grid_barrier(++bar * 128u);
        }

        // ---- act: reduce partials + drive + activation + update ----
        float s[4] = {0.f, 0.f, 0.f, 0.f};
        if (t > 0) {
            #pragma unroll
            for (int kq = 0; kq < 8; ++kq) {
                const float4 p = *reinterpret_cast<const float4*>(
                    &g_partial[((kq * 128 + b_a) << 10) + n_a]);
                s[0] += p.x; s[1] += p.y; s[2] += p.z; s[3] += p.w;
            }
        }
        {
            const float* uu = &Us[(tid >> 4) * 24];
            #pragma unroll
            for (int j = 0; j < 4; ++j) {
                const float* bp = &Bs[(nl_a + j) * 24];
                float d = 0.f;
                #pragma unroll
                for (int i = 0; i < INDIM; ++i) d = fmaf(uu[i], bp[i], d);
                s[j] += d;
            }
        }
        float rn[4];
        #pragma unroll
        for (int j = 0; j < 4; ++j) {
            const float e = __expf(fmaf(-0.8f, s[j], 6.0f));
            const float act = __fdividef(16.0f, 1.0f + e);
            rn[j] = fmaf(an[j], act - rr[j], rr[j]);
            rr[j] = rn[j];
        }
        float4 rno = {rn[0], rn[1], rn[2], rn[3]};
        *reinterpret_cast<float4*>(&out[((size_t)b_a * SEQ + t) * NN + n_a]) = rno;
        if (t == SEQ - 1)
            *reinterpret_cast<float4*>(&out[(size_t)BATCH * SEQ * NN + b_a * NN + n_a]) = rno;

        union { unsigned short u16[4]; uint2 v; } ab;
        #pragma unroll
        for (int j = 0; j < 4; ++j) {
            __nv_bfloat16 h = __float2bfloat16(fmaxf(rn[j], 0.f));
            ab.u16[j] = *reinterpret_cast<unsigned short*>(&h);
        }
        *reinterpret_cast<uint2*>(g_A + b_a * NN + n_a) = ab.v;

        grid_barrier(++bar * 128u);
    }
}

// ---------------- launch (2 graph nodes) ----------------
extern "C" void kernel_launch(void* const* d_in, const int* in_sizes, int n_in,
                              void* d_out, int out_size) {
    const float* u   = (const float*)d_in[0];
    const float* W   = (const float*)d_in[1];
    const float* Bm  = (const float*)d_in[2];
    const float* ds  = (const float*)d_in[3];
    const float* tau = (const float*)d_in[4];
    float* out = (float*)d_out;

    static int smem_set = 0;
    if (!smem_set) {
        cudaFuncSetAttribute(persist_kernel, cudaFuncAttributeMaxDynamicSharedMemorySize, SMEM_TOTAL);
        smem_set = 1;
    }

    wprep_kernel<<<1024, 128>>>(W, ds);
    persist_kernel<<<128, 256, SMEM_TOTAL>>>(u, Bm, tau, out);
}

// round 6
// speedup vs baseline: 3.9546x; 1.1752x over previous
#include <cuda_runtime.h>
#include <cuda_bf16.h>
#include <cstdint>

#define NN     1024
#define BATCH  128
#define SEQ    500
#define INDIM  24

// ---------------- device scratch (alloc-free) ----------------
__device__ __align__(16) __nv_bfloat16 g_A[2][BATCH * NN];  // double-buffered relu(r) bf16
__device__ __align__(16) __nv_bfloat16 g_Whi[NN * NN];      // [n][k], sign folded
__device__ __align__(16) __nv_bfloat16 g_Wlo[NN * NN];      // bf16 residual
__device__ unsigned g_ctr;                                  // grid barrier counter

// ---------------- PTX helpers (portable, sm_80+) ----------------
__device__ __forceinline__ uint32_t smem_u32(const void* p) {
    uint32_t a;
    asm("{ .reg .u64 t; cvta.to.shared.u64 t, %1; cvt.u32.u64 %0, t; }" : "=r"(a) : "l"(p));
    return a;
}
__device__ __forceinline__ void ldsm_x4(uint32_t* r, uint32_t addr) {
    asm volatile("ldmatrix.sync.aligned.m8n8.x4.shared.b16 {%0,%1,%2,%3}, [%4];"
        : "=r"(r[0]), "=r"(r[1]), "=r"(r[2]), "=r"(r[3]) : "r"(addr));
}
__device__ __forceinline__ void mma_bf16(float* d, const uint32_t* a, const uint32_t* b) {
    asm volatile("mma.sync.aligned.m16n8k16.row.col.f32.bf16.bf16.f32 "
        "{%0,%1,%2,%3}, {%4,%5,%6,%7}, {%8,%9}, {%0,%1,%2,%3};"
        : "+f"(d[0]), "+f"(d[1]), "+f"(d[2]), "+f"(d[3])
        : "r"(a[0]), "r"(a[1]), "r"(a[2]), "r"(a[3]), "r"(b[0]), "r"(b[1]));
}

// grid barrier: 128 CTAs co-resident (1/SM)
__device__ __forceinline__ void grid_barrier(unsigned target) {
    __syncthreads();
    if (threadIdx.x == 0) {
        asm volatile("red.release.gpu.add.u32 [%0], %1;" :: "l"(&g_ctr), "r"(1u) : "memory");
        unsigned v;
        do {
            asm volatile("ld.acquire.gpu.b32 %0, [%1];" : "=r"(v) : "l"(&g_ctr) : "memory");
        } while (v < target);
    }
    __syncthreads();
}

// ---------------- W prep: fold dales sign, split hi/lo; reset ctr ----------------
__global__ __launch_bounds__(128) void wprep_kernel(const float* __restrict__ W,
                                                    const float* __restrict__ ds) {
    int gid = blockIdx.x * 128 + threadIdx.x;
    if (gid == 0) g_ctr = 0u;
    int base = gid << 3;
    int k0 = base & (NN - 1);
    union { unsigned short u[8]; uint4 v; } hi, lo;
    #pragma unroll
    for (int j = 0; j < 8; ++j) {
        float w = W[base + j] * ds[k0 + j];
        __nv_bfloat16 h = __float2bfloat16(w);
        __nv_bfloat16 l = __float2bfloat16(w - __bfloat162float(h));
        hi.u[j] = *reinterpret_cast<unsigned short*>(&h);
        lo.u[j] = *reinterpret_cast<unsigned short*>(&l);
    }
    *reinterpret_cast<uint4*>(g_Whi + base) = hi.v;
    *reinterpret_cast<uint4*>(g_Wlo + base) = lo.v;
}

// ---------------- persistent kernel ----------------
// CTA c: mg = c>>5 (32-batch group), ntile = c&31 (32-neuron tile). Full K=1024.
// Warps: h = wid>>2 (k half), mi = (wid>>1)&1 (m16), ni = wid&1 (n16).
#define LDA 1032                        // 1024 + 8 pad elems; 2064 B row stride
#define SW_HI 0
#define SW_LO 66048
#define SA    132096
#define SM_XS 198144                    // 32 x 33 fp32 reduce/x buffer
#define SM_BS 202368                    // 32 x 24 fp32
#define SM_US 205440                    // 32 x 24 fp32
#define SMEM_TOTAL 208512

__global__ __launch_bounds__(256, 1) void persist_kernel(
    const float* __restrict__ u,
    const float* __restrict__ Bmat,
    const float* __restrict__ tau,
    float* __restrict__ out)
{
    extern __shared__ char smem[];
    const uint32_t sb = smem_u32(smem);
    const int tid  = threadIdx.x;
    const int lane = tid & 31;
    const int wid  = tid >> 5;
    const int h  = wid >> 2;
    const int mi = (wid >> 1) & 1;
    const int ni = wid & 1;
    const int c  = blockIdx.x;
    const int ntile = c & 31;
    const int mg    = c >> 5;

    // ---- persistent W tile (32 n-rows x 1024 k, hi+lo), loaded once ----
    #pragma unroll 4
    for (int i = tid; i < 4096; i += 256) {            // 32 rows x 128 uint4
        const int row = i >> 7, c16 = i & 127;
        const size_t gsrc = (size_t)(ntile * 32 + row) * NN + c16 * 8;
        const int dst = (row * LDA + c16 * 8) * 2;
        *reinterpret_cast<uint4*>(smem + SW_HI + dst) = *reinterpret_cast<const uint4*>(g_Whi + gsrc);
        *reinterpret_cast<uint4*>(smem + SW_LO + dst) = *reinterpret_cast<const uint4*>(g_Wlo + gsrc);
    }
    // ---- persistent B tile (32 x 24 fp32), once ----
    float* Bs = reinterpret_cast<float*>(smem + SM_BS);
    for (int i = tid; i < 192; i += 256) {
        const int row = i / 6, q = i % 6;
        *reinterpret_cast<float4*>(&Bs[row * 24 + q * 4]) =
            *reinterpret_cast<const float4*>(Bmat + (size_t)(ntile * 32 + row) * INDIM + q * 4);
    }

    // ---- act-role constants + register state ----
    const int bl  = tid >> 3;                // 0..31 batch-local
    const int nlq = (tid & 7) * 4;           // n-local (x4)
    const int b_g = mg * 32 + bl;
    const int n_g = ntile * 32 + nlq;
    float an[4], rr[4];
    {
        const float4 t4 = *reinterpret_cast<const float4*>(&tau[n_g]);
        an[0] = 0.1f / t4.x; an[1] = 0.1f / t4.y; an[2] = 0.1f / t4.z; an[3] = 0.1f / t4.w;
        rr[0] = rr[1] = rr[2] = rr[3] = 0.f;
    }
    float* Us = reinterpret_cast<float*>(smem + SM_US);
    float* xs = reinterpret_cast<float*>(smem + SM_XS);

    // ldmatrix lane maps
    const int ra = lane & 15, ca = (lane >> 4) << 3;
    const int rbw = ((lane >> 4) & 1) * 8 + (lane & 7);
    const int cbw = ((lane >> 3) & 1) << 3;
    const int rq = lane >> 2, cq = (lane & 3) * 2;

    for (int t = 0; t < SEQ; ++t) {
        // ---- stage per-step loads ----
        if (tid < 192) {                                  // u[b,t,:] for 32 batches
            const int bi = tid / 6, q = tid % 6;
            *reinterpret_cast<float4*>(&Us[bi * 24 + q * 4]) =
                *reinterpret_cast<const float4*>(u + ((size_t)(mg * 32 + bi) * SEQ + t) * INDIM + q * 4);
        }
        if (t > 0) {
            const __nv_bfloat16* Asrc = g_A[(t - 1) & 1];
            #pragma unroll 8
            for (int i = tid; i < 4096; i += 256) {       // 32 rows x 128 uint4
                const int row = i >> 7, c16 = i & 127;
                *reinterpret_cast<uint4*>(smem + SA + (row * LDA + c16 * 8) * 2) =
                    *reinterpret_cast<const uint4*>(Asrc + (size_t)(mg * 32 + row) * NN + c16 * 8);
            }
        }
        __syncthreads();

        if (t > 0) {
            // ---- GEMM: warp (h,mi,ni) does m16 x n16 over its k-half ----
            float acc[2][4];
            #pragma unroll
            for (int nq = 0; nq < 2; ++nq)
                #pragma unroll
                for (int q = 0; q < 4; ++q) acc[nq][q] = 0.f;

            #pragma unroll 4
            for (int ks = 0; ks < 32; ++ks) {
                const int k0 = h * 512 + ks * 16;
                uint32_t a4[4], bh4[4], bl4[4];
                ldsm_x4(a4,  sb + SA    + ((mi * 16 + ra) * LDA + k0 + ca) * 2);
                ldsm_x4(bh4, sb + SW_HI + ((ni * 16 + rbw) * LDA + k0 + cbw) * 2);
                ldsm_x4(bl4, sb + SW_LO + ((ni * 16 + rbw) * LDA + k0 + cbw) * 2);
                mma_bf16(acc[0], a4, &bh4[0]);
                mma_bf16(acc[0], a4, &bl4[0]);
                mma_bf16(acc[1], a4, &bh4[2]);
                mma_bf16(acc[1], a4, &bl4[2]);
            }

            // ---- intra-CTA k-reduce through xs ----
            const int row0 = mi * 16 + rq;
            if (h == 1) {
                #pragma unroll
                for (int nq = 0; nq < 2; ++nq) {
                    const int col = ni * 16 + nq * 8 + cq;
                    xs[row0 * 33 + col]           = acc[nq][0];
                    xs[row0 * 33 + col + 1]       = acc[nq][1];
                    xs[(row0 + 8) * 33 + col]     = acc[nq][2];
                    xs[(row0 + 8) * 33 + col + 1] = acc[nq][3];
                }
            }
            __syncthreads();
            if (h == 0) {
                #pragma unroll
                for (int nq = 0; nq < 2; ++nq) {
                    const int col = ni * 16 + nq * 8 + cq;
                    xs[row0 * 33 + col]           += acc[nq][0];
                    xs[row0 * 33 + col + 1]       += acc[nq][1];
                    xs[(row0 + 8) * 33 + col]     += acc[nq][2];
                    xs[(row0 + 8) * 33 + col + 1] += acc[nq][3];
                }
            }
            __syncthreads();
        }

        // ---- act: x + drive -> activation -> state update ----
        float s[4];
        #pragma unroll
        for (int j = 0; j < 4; ++j)
            s[j] = (t > 0) ? xs[bl * 33 + nlq + j] : 0.f;
        {
            const float* uu = &Us[bl * 24];
            #pragma unroll
            for (int j = 0; j < 4; ++j) {
                const float* bp = &Bs[(nlq + j) * 24];
                float d = 0.f;
                #pragma unroll
                for (int i = 0; i < INDIM; ++i) d = fmaf(uu[i], bp[i], d);
                s[j] += d;
            }
        }
        float rn[4];
        #pragma unroll
        for (int j = 0; j < 4; ++j) {
            const float e = __expf(fmaf(-0.8f, s[j], 6.0f));
            const float act = __fdividef(16.0f, 1.0f + e);
            rn[j] = fmaf(an[j], act - rr[j], rr[j]);
            rr[j] = rn[j];
        }
        float4 rno = {rn[0], rn[1], rn[2], rn[3]};
        *reinterpret_cast<float4*>(&out[((size_t)b_g * SEQ + t) * NN + n_g]) = rno;
        if (t == SEQ - 1)
            *reinterpret_cast<float4*>(&out[(size_t)BATCH * SEQ * NN + b_g * NN + n_g]) = rno;

        union { unsigned short u16[4]; uint2 v; } ab;
        #pragma unroll
        for (int j = 0; j < 4; ++j) {
            __nv_bfloat16 hb = __float2bfloat16(fmaxf(rn[j], 0.f));
            ab.u16[j] = *reinterpret_cast<unsigned short*>(&hb);
        }
        *reinterpret_cast<uint2*>(g_A[t & 1] + (size_t)b_g * NN + n_g) = ab.v;

        if (t + 1 < SEQ) grid_barrier((unsigned)(t + 1) * 128u);
    }
}

// ---------------- launch (2 graph nodes) ----------------
extern "C" void kernel_launch(void* const* d_in, const int* in_sizes, int n_in,
                              void* d_out, int out_size) {
    const float* u   = (const float*)d_in[0];
    const float* W   = (const float*)d_in[1];
    const float* Bm  = (const float*)d_in[2];
    const float* ds  = (const float*)d_in[3];
    const float* tau = (const float*)d_in[4];
    float* out = (float*)d_out;

    static int smem_set = 0;
    if (!smem_set) {
        cudaFuncSetAttribute(persist_kernel, cudaFuncAttributeMaxDynamicSharedMemorySize, SMEM_TOTAL);
        smem_set = 1;
    }

    wprep_kernel<<<1024, 128>>>(W, ds);
    persist_kernel<<<128, 256, SMEM_TOTAL>>>(u, Bm, tau, out);
}